// round 15
// baseline (speedup 1.0000x reference)
#include <cuda_runtime.h>
#include <cuda_fp16.h>
#include <cstdint>

// ============================================================================
// FeedForwardLoRA on GB300 (sm_103) — fp16 mma.sync path, R15.
// R14 falsified the LTS-cap theory (L2% fell, perf regressed): the real R12
// binder is per-SMSP latency exposure at 2 warps/SMSP + single-chunk barrier
// alignment. R15: back to 128x128 tiles, but 3 CTAs/SM (NS=2, 73728B smem/CTA,
// 3x73728=221184B/SM) -> 12 warps/SM in three independent barrier domains.
// __launch_bounds__(128,3) caps regs at 170 (acc+frags=168). Inner loop =
// R12's JIT schedule unchanged.
//
//   W1h = f16_rn(W1 + 0.25 * B1[a] @ A1[a])
//   W2h = f16_rn(W2 + 0.25 * B2[a] @ A2[a])
//   xh  = f16_rn(x)
//   h   = f16_rn(relu(xh @ W1h^T))       GEMM1: M=16384 N=4096 K=1024
//   out = h @ W2h^T  (fp32 out)          GEMM2: M=16384 N=1024 K=4096
// ============================================================================

#define TOK     16384
#define DMODEL  1024
#define DFF     4096
#define RANKL   4

#define TM   128          // CTA M tile
#define TN   128          // CTA N tile
#define TKC  64           // K chunk (halves) = 128B per row
#define NS   2            // cp.async pipeline stages
#define PITCHB 144        // smem row pitch in bytes (128B data + 16B skew)

#define SM_A_BYTES (TM * PITCHB)                // 18432 B
#define SM_B_BYTES (TN * PITCHB)                // 18432 B
#define STAGE_BYTES (SM_A_BYTES + SM_B_BYTES)   // 36864 B
#define SMEM_TOTAL (NS * STAGE_BYTES)           // 73728 B (x3 CTAs = 221184/SM)

// ---------------------------------------------------------------------------
// Scratch (static __device__ arrays — the sanctioned no-alloc workaround)
// ---------------------------------------------------------------------------
__device__ __half g_xh [(size_t)TOK * DMODEL];  //  32 MB
__device__ __half g_h  [(size_t)TOK * DFF];     // 128 MB
__device__ __half g_w1h[(size_t)DFF * DMODEL];  //   8 MB
__device__ __half g_w2h[(size_t)DMODEL * DFF];  //   8 MB

// ---------------------------------------------------------------------------
// Helpers
// ---------------------------------------------------------------------------
__device__ __forceinline__ uint32_t smem_u32(const void* p) {
    uint32_t a;
    asm("{ .reg .u64 t; cvta.to.shared.u64 t, %1; cvt.u32.u64 %0, t; }"
        : "=r"(a) : "l"(p));
    return a;
}

#define CPA16(smem_addr, gptr) \
    asm volatile("cp.async.cg.shared.global [%0], [%1], 16;" \
                 :: "r"(smem_addr), "l"(gptr))
#define CP_COMMIT()  asm volatile("cp.async.commit_group;" ::: "memory")
#define CP_WAIT_0()  asm volatile("cp.async.wait_group 0;" ::: "memory")

#define LDSM_X4(r0, r1, r2, r3, addr) \
    asm volatile("ldmatrix.sync.aligned.m8n8.x4.shared.b16 {%0,%1,%2,%3}, [%4];" \
                 : "=r"(r0), "=r"(r1), "=r"(r2), "=r"(r3) : "r"(addr))

// D += A * B   (m16n8k16, fp16 inputs, fp32 accumulate)
__device__ __forceinline__ void mma16(float* d, const uint32_t* a,
                                      uint32_t b0, uint32_t b1) {
    asm volatile(
        "mma.sync.aligned.m16n8k16.row.col.f32.f16.f16.f32 "
        "{%0,%1,%2,%3}, {%4,%5,%6,%7}, {%8,%9}, {%0,%1,%2,%3};"
        : "+f"(d[0]), "+f"(d[1]), "+f"(d[2]), "+f"(d[3])
        : "r"(a[0]), "r"(a[1]), "r"(a[2]), "r"(a[3]), "r"(b0), "r"(b1));
}

// ---------------------------------------------------------------------------
// GEMM: C[M, NGLOB] = op(A[M,KDIM] @ B[NGLOB,KDIM]^T), fp16 in, fp32 acc.
// STORE_HALF_RELU: C = f16_rn(relu(.)) as half.  Else: C = fp32.
// Grid (NGLOB/TN, M/TM), 128 threads = 4 warps of 64x64 tiles (2x2 layout).
// 3 CTAs per SM. All dims divide exactly — no tails anywhere.
// ---------------------------------------------------------------------------
template <bool STORE_HALF_RELU, int KDIM, int NGLOB>
__global__ void __launch_bounds__(128, 3)
gemm_f16(const __half* __restrict__ Ag, const __half* __restrict__ Bg,
         void* __restrict__ Cg_)
{
    constexpr int KT = KDIM / TKC;
    extern __shared__ char smem[];
    const uint32_t sbase = smem_u32(smem);
    const int tid = threadIdx.x;
    const int m0 = blockIdx.y * TM;
    const int n0 = blockIdx.x * TN;

    // ---- async-load geometry: thread -> (row, 16B chunk) --------------------
    const int lrow = tid >> 3;          // 0..15
    const int lchk = tid & 7;           // 0..7

    // Advancing gmem base pointers.
    const __half* agp = Ag + (size_t)(m0 + lrow) * KDIM + lchk * 8;
    const __half* bgp = Bg + (size_t)(n0 + lrow) * KDIM + lchk * 8;
    const uint32_t swr = (uint32_t)lrow * PITCHB + (uint32_t)lchk * 16;

    // ---- compute geometry ---------------------------------------------------
    const int lane = tid & 31;
    const int w = tid >> 5;             // 0..3
    const int wm = (w & 1) * 64;        // warp M offset within CTA tile
    const int wn = (w >> 1) * 64;       // warp N offset
    const int g = lane >> 2;
    const int c = lane & 3;

    // ldmatrix lane -> (matrix id, row-in-matrix)
    const int lsub = lane >> 3;
    const int lr8  = lane & 7;
    const uint32_t arow = (uint32_t)(wm + (lsub & 1) * 8 + lr8);
    const uint32_t brow = (uint32_t)(wn + (lsub & 1) * 8 + lr8);
    const uint32_t koff = (uint32_t)(lsub >> 1) * 16;
    const uint32_t aoff = arow * PITCHB + koff;               // within stage
    const uint32_t boff = SM_A_BYTES + brow * PITCHB + koff;

    float acc[4][8][4];
#pragma unroll
    for (int mi = 0; mi < 4; mi++)
#pragma unroll
        for (int ni = 0; ni < 8; ni++)
#pragma unroll
            for (int q = 0; q < 4; q++) acc[mi][ni][q] = 0.0f;

    // ---- prologue: stage 0 --------------------------------------------------
    {
        const uint32_t sw = sbase + swr;
#pragma unroll
        for (int j = 0; j < 8; j++) {
            CPA16(sw + (uint32_t)j * (16 * PITCHB), agp + (size_t)(16 * j) * KDIM);
            CPA16(sw + SM_A_BYTES + (uint32_t)j * (16 * PITCHB),
                  bgp + (size_t)(16 * j) * KDIM);
        }
        CP_COMMIT();
    }
    agp += TKC;                         // prefetch cursor: stage kt+1
    bgp += TKC;

    // ---- main loop ----------------------------------------------------------
    for (int kt = 0; kt < KT; kt++) {
        CP_WAIT_0();                    // stage kt landed (all groups drained)
        __syncthreads();                // cross-thread visibility + slot reuse

        const int slot = kt & 1;
        const bool do_pf = (kt + 1) < KT;
        const uint32_t sA = sbase + (uint32_t)slot * STAGE_BYTES;
        const uint32_t aB = sA + aoff;
        const uint32_t bB = sA + boff;
        const uint32_t swp = sbase + (uint32_t)(slot ^ 1) * STAGE_BYTES + swr;

        // Fragments: B double-buffered across ks; A rotates per group.
        uint32_t bf[2][4][4];
        uint32_t af[2][4];

        // Preload: bf[0][0..3] + af[group 0]  (5 ldsm)
#pragma unroll
        for (int pi = 0; pi < 4; pi++)
            LDSM_X4(bf[0][pi][0], bf[0][pi][1], bf[0][pi][2], bf[0][pi][3],
                    bB + (uint32_t)pi * (16 * PITCHB));
        LDSM_X4(af[0][0], af[0][1], af[0][2], af[0][3], aB);

#pragma unroll
        for (int ks = 0; ks < 4; ks++) {            // 4 x k16 = K chunk 64
            const int cur = ks & 1, nxt = cur ^ 1;
            // Spread prefetch of stage kt+1: quarter ks (4 cp.async)
            if (do_pf) {
#pragma unroll
                for (int j = 2 * ks; j < 2 * ks + 2; j++) {
                    CPA16(swp + (uint32_t)j * (16 * PITCHB),
                          agp + (size_t)(16 * j) * KDIM);
                    CPA16(swp + SM_A_BYTES + (uint32_t)j * (16 * PITCHB),
                          bgp + (size_t)(16 * j) * KDIM);
                }
            }
#pragma unroll
            for (int mi = 0; mi < 4; mi++) {
                const int gidx = ks * 4 + mi;
                const int ap = gidx & 1, an = ap ^ 1;   // af parity
                const int ng = gidx + 1;
                mma16(acc[mi][0], af[ap], bf[cur][0][0], bf[cur][0][2]);
                mma16(acc[mi][1], af[ap], bf[cur][0][1], bf[cur][0][3]);
                if (ng < 16)
                    LDSM_X4(af[an][0], af[an][1], af[an][2], af[an][3],
                            aB + (uint32_t)(ng & 3) * (16 * PITCHB)
                               + (uint32_t)(ng >> 2) * 32);
                mma16(acc[mi][2], af[ap], bf[cur][1][0], bf[cur][1][2]);
                mma16(acc[mi][3], af[ap], bf[cur][1][1], bf[cur][1][3]);
                if (ks < 3)             // B fragment pi=mi for ks+1 (JIT)
                    LDSM_X4(bf[nxt][mi][0], bf[nxt][mi][1],
                            bf[nxt][mi][2], bf[nxt][mi][3],
                            bB + (uint32_t)mi * (16 * PITCHB)
                               + (uint32_t)(ks + 1) * 32);
                mma16(acc[mi][4], af[ap], bf[cur][2][0], bf[cur][2][2]);
                mma16(acc[mi][5], af[ap], bf[cur][2][1], bf[cur][2][3]);
                mma16(acc[mi][6], af[ap], bf[cur][3][0], bf[cur][3][2]);
                mma16(acc[mi][7], af[ap], bf[cur][3][1], bf[cur][3][3]);
            }
        }
        CP_COMMIT();                    // one group per iteration (maybe empty)
        agp += TKC;
        bgp += TKC;
    }

    // ---- epilogue -----------------------------------------------------------
#pragma unroll
    for (int mi = 0; mi < 4; mi++) {
        const int r0 = m0 + wm + mi * 16 + g;
        const int r1 = r0 + 8;
#pragma unroll
        for (int ni = 0; ni < 8; ni++) {
            const int cc = n0 + wn + ni * 8 + 2 * c;
            if (STORE_HALF_RELU) {
                __half* C = (__half*)Cg_;
                __half2 v0 = __floats2half2_rn(fmaxf(acc[mi][ni][0], 0.0f),
                                               fmaxf(acc[mi][ni][1], 0.0f));
                __half2 v1 = __floats2half2_rn(fmaxf(acc[mi][ni][2], 0.0f),
                                               fmaxf(acc[mi][ni][3], 0.0f));
                *(__half2*)(C + (size_t)r0 * NGLOB + cc) = v0;
                *(__half2*)(C + (size_t)r1 * NGLOB + cc) = v1;
            } else {
                float* C = (float*)Cg_;
                *(float2*)(C + (size_t)r0 * NGLOB + cc) =
                    make_float2(acc[mi][ni][0], acc[mi][ni][1]);
                *(float2*)(C + (size_t)r1 * NGLOB + cc) =
                    make_float2(acc[mi][ni][2], acc[mi][ni][3]);
            }
        }
    }
}

// ---------------------------------------------------------------------------
// Weight merge: Wm = f16_rn(W + 0.25 * B[a] @ A[a]),  W:[OUT,IN] row-major
// ---------------------------------------------------------------------------
__global__ void merge_w(const float* __restrict__ W, const float* __restrict__ A,
                        const float* __restrict__ Bm, const int* __restrict__ aid,
                        __half* __restrict__ Wm, int OUT, int IN)
{
    const int in4 = IN >> 2;
    const int i = blockIdx.x * blockDim.x + threadIdx.x;
    if (i >= OUT * in4) return;
    const int f = i / in4;
    const int d = (i - f * in4) << 2;
    const int a = aid[0];

    const float* Aa = A + (size_t)a * RANKL * IN;
    const float* Ba = Bm + (size_t)a * OUT * RANKL + (size_t)f * RANKL;
    const float b0 = Ba[0] * 0.25f, b1 = Ba[1] * 0.25f,
                b2 = Ba[2] * 0.25f, b3 = Ba[3] * 0.25f;

    float4 w = ((const float4*)W)[i];
    const float4 a0 = *(const float4*)(Aa + 0 * (size_t)IN + d);
    const float4 a1 = *(const float4*)(Aa + 1 * (size_t)IN + d);
    const float4 a2 = *(const float4*)(Aa + 2 * (size_t)IN + d);
    const float4 a3 = *(const float4*)(Aa + 3 * (size_t)IN + d);

    __half2 lo = __floats2half2_rn(w.x + b0 * a0.x + b1 * a1.x + b2 * a2.x + b3 * a3.x,
                                   w.y + b0 * a0.y + b1 * a1.y + b2 * a2.y + b3 * a3.y);
    __half2 hi = __floats2half2_rn(w.z + b0 * a0.z + b1 * a1.z + b2 * a2.z + b3 * a3.z,
                                   w.w + b0 * a0.w + b1 * a1.w + b2 * a2.w + b3 * a3.w);
    __half2* dst = (__half2*)(Wm + (size_t)i * 4);
    dst[0] = lo;
    dst[1] = hi;
}

// ---------------------------------------------------------------------------
// Activation pre-round: xh = f16_rn(x)
// ---------------------------------------------------------------------------
__global__ void to_half(const float4* __restrict__ in, __half* __restrict__ out,
                        int n4)
{
    const int i = blockIdx.x * blockDim.x + threadIdx.x;
    if (i >= n4) return;
    float4 v = in[i];
    __half2* dst = (__half2*)(out + (size_t)i * 4);
    dst[0] = __floats2half2_rn(v.x, v.y);
    dst[1] = __floats2half2_rn(v.z, v.w);
}

// ---------------------------------------------------------------------------
// Launch
// ---------------------------------------------------------------------------
extern "C" void kernel_launch(void* const* d_in, const int* in_sizes, int n_in,
                              void* d_out, int out_size)
{
    const float* x   = (const float*)d_in[0];
    const float* W1  = (const float*)d_in[1];
    const float* A1  = (const float*)d_in[2];
    const float* B1  = (const float*)d_in[3];
    const float* W2  = (const float*)d_in[4];
    const float* A2  = (const float*)d_in[5];
    const float* B2  = (const float*)d_in[6];
    const int*   aid = (const int*)d_in[7];
    float* out = (float*)d_out;

    __half *xh, *h, *w1h, *w2h;
    cudaGetSymbolAddress((void**)&xh,  g_xh);
    cudaGetSymbolAddress((void**)&h,   g_h);
    cudaGetSymbolAddress((void**)&w1h, g_w1h);
    cudaGetSymbolAddress((void**)&w2h, g_w2h);

    cudaFuncSetAttribute((gemm_f16<true, DMODEL, DFF>),
                         cudaFuncAttributeMaxDynamicSharedMemorySize, SMEM_TOTAL);
    cudaFuncSetAttribute((gemm_f16<false, DFF, DMODEL>),
                         cudaFuncAttributeMaxDynamicSharedMemorySize, SMEM_TOTAL);

    // 1) x -> fp16
    const int n4x = TOK * DMODEL / 4;
    to_half<<<(n4x + 255) / 256, 256>>>((const float4*)x, xh, n4x);

    // 2) fold LoRA into weights, round to fp16
    const int n4w = DFF * DMODEL / 4;
    merge_w<<<(n4w + 255) / 256, 256>>>(W1, A1, B1, aid, w1h, DFF, DMODEL);
    merge_w<<<(n4w + 255) / 256, 256>>>(W2, A2, B2, aid, w2h, DMODEL, DFF);

    // 3) h = f16(relu(xh @ w1h^T))     M=16384, N=4096, K=1024
    dim3 g1(DFF / TN, TOK / TM);
    gemm_f16<true, DMODEL, DFF><<<g1, 128, SMEM_TOTAL>>>(xh, w1h, (void*)h);

    // 4) out = h @ w2h^T  (fp32)       M=16384, N=1024, K=4096
    dim3 g2(DMODEL / TN, TOK / TM);
    gemm_f16<false, DFF, DMODEL><<<g2, 128, SMEM_TOTAL>>>(h, w2h, (void*)out);
}

// round 16
// speedup vs baseline: 1.5009x; 1.5009x over previous
#include <cuda_runtime.h>
#include <cuda_fp16.h>
#include <cstdint>

// ============================================================================
// FeedForwardLoRA on GB300 (sm_103) — fp16 mma.sync path, R16.
// R14 (1 CTA/SM) and R15 (3 CTAs/SM) both lost to R12 (2 CTAs/SM, 707us):
// config search done. R12 residual analysis: per-CTA tensor duty 65% and SM
// tensor busy 65.8% are EQUAL -> the two co-resident CTAs run phase-locked
// in-phase (independent phases would give ~88%). R16 = R12 + a half-chunk
// (~1600cyc) start offset for the odd member of each co-resident pair
// (classic placement pairs bids b and b+148), issued after the prologue
// cp.async so the spin overlaps load latency.
//
//   W1h = f16_rn(W1 + 0.25 * B1[a] @ A1[a])
//   W2h = f16_rn(W2 + 0.25 * B2[a] @ A2[a])
//   xh  = f16_rn(x)
//   h   = f16_rn(relu(xh @ W1h^T))       GEMM1: M=16384 N=4096 K=1024
//   out = h @ W2h^T  (fp32 out)          GEMM2: M=16384 N=1024 K=4096
// ============================================================================

#define TOK     16384
#define DMODEL  1024
#define DFF     4096
#define RANKL   4

#define TM   128          // CTA M tile
#define TN   128          // CTA N tile
#define TKC  64           // K chunk (halves) = 128B per row
#define NS   3            // cp.async pipeline stages
#define PITCHB 144        // smem row pitch in bytes (128B data + 16B skew)

#define SM_A_BYTES (TM * PITCHB)                // 18432 B
#define SM_B_BYTES (TN * PITCHB)                // 18432 B
#define STAGE_BYTES (SM_A_BYTES + SM_B_BYTES)   // 36864 B
#define SMEM_TOTAL (NS * STAGE_BYTES)           // 110592 B (x2 CTAs = 221184/SM)

#define PHASE_SPIN 1600   // ~half of the measured per-chunk wall (3143 cyc)

// ---------------------------------------------------------------------------
// Scratch (static __device__ arrays — the sanctioned no-alloc workaround)
// ---------------------------------------------------------------------------
__device__ __half g_xh [(size_t)TOK * DMODEL];  //  32 MB
__device__ __half g_h  [(size_t)TOK * DFF];     // 128 MB
__device__ __half g_w1h[(size_t)DFF * DMODEL];  //   8 MB
__device__ __half g_w2h[(size_t)DMODEL * DFF];  //   8 MB

// ---------------------------------------------------------------------------
// Helpers
// ---------------------------------------------------------------------------
__device__ __forceinline__ uint32_t smem_u32(const void* p) {
    uint32_t a;
    asm("{ .reg .u64 t; cvta.to.shared.u64 t, %1; cvt.u32.u64 %0, t; }"
        : "=r"(a) : "l"(p));
    return a;
}

#define CPA16(smem_addr, gptr) \
    asm volatile("cp.async.cg.shared.global [%0], [%1], 16;" \
                 :: "r"(smem_addr), "l"(gptr))
#define CP_COMMIT()  asm volatile("cp.async.commit_group;" ::: "memory")
#define CP_WAIT_1()  asm volatile("cp.async.wait_group 1;" ::: "memory")

#define LDSM_X4(r0, r1, r2, r3, addr) \
    asm volatile("ldmatrix.sync.aligned.m8n8.x4.shared.b16 {%0,%1,%2,%3}, [%4];" \
                 : "=r"(r0), "=r"(r1), "=r"(r2), "=r"(r3) : "r"(addr))

// D += A * B   (m16n8k16, fp16 inputs, fp32 accumulate)
__device__ __forceinline__ void mma16(float* d, const uint32_t* a,
                                      uint32_t b0, uint32_t b1) {
    asm volatile(
        "mma.sync.aligned.m16n8k16.row.col.f32.f16.f16.f32 "
        "{%0,%1,%2,%3}, {%4,%5,%6,%7}, {%8,%9}, {%0,%1,%2,%3};"
        : "+f"(d[0]), "+f"(d[1]), "+f"(d[2]), "+f"(d[3])
        : "r"(a[0]), "r"(a[1]), "r"(a[2]), "r"(a[3]), "r"(b0), "r"(b1));
}

// ---------------------------------------------------------------------------
// GEMM: C[M, NGLOB] = op(A[M,KDIM] @ B[NGLOB,KDIM]^T), fp16 in, fp32 acc.
// STORE_HALF_RELU: C = f16_rn(relu(.)) as half.  Else: C = fp32.
// Grid (NGLOB/TN, M/TM), 128 threads = 4 warps of 64x64 tiles (2x2 layout).
// 2 CTAs per SM. All dims divide exactly — no tails anywhere.
// ---------------------------------------------------------------------------
template <bool STORE_HALF_RELU, int KDIM, int NGLOB>
__global__ void __launch_bounds__(128, 2)
gemm_f16(const __half* __restrict__ Ag, const __half* __restrict__ Bg,
         void* __restrict__ Cg_)
{
    constexpr int KT = KDIM / TKC;
    extern __shared__ char smem[];
    const uint32_t sbase = smem_u32(smem);
    const int tid = threadIdx.x;
    const int m0 = blockIdx.y * TM;
    const int n0 = blockIdx.x * TN;

    // ---- async-load geometry: thread -> (row, 16B chunk) --------------------
    const int lrow = tid >> 3;          // 0..15
    const int lchk = tid & 7;           // 0..7

    // Advancing gmem base pointers.
    const __half* agp = Ag + (size_t)(m0 + lrow) * KDIM + lchk * 8;
    const __half* bgp = Bg + (size_t)(n0 + lrow) * KDIM + lchk * 8;
    const uint32_t swr = (uint32_t)lrow * PITCHB + (uint32_t)lchk * 16;

    // ---- compute geometry ---------------------------------------------------
    const int lane = tid & 31;
    const int w = tid >> 5;             // 0..3
    const int wm = (w & 1) * 64;        // warp M offset within CTA tile
    const int wn = (w >> 1) * 64;       // warp N offset
    const int g = lane >> 2;
    const int c = lane & 3;

    // ldmatrix lane -> (matrix id, row-in-matrix)
    const int lsub = lane >> 3;
    const int lr8  = lane & 7;
    const uint32_t arow = (uint32_t)(wm + (lsub & 1) * 8 + lr8);
    const uint32_t brow = (uint32_t)(wn + (lsub & 1) * 8 + lr8);
    const uint32_t koff = (uint32_t)(lsub >> 1) * 16;
    const uint32_t aoff = arow * PITCHB + koff;               // within stage
    const uint32_t boff = SM_A_BYTES + brow * PITCHB + koff;

    float acc[4][8][4];
#pragma unroll
    for (int mi = 0; mi < 4; mi++)
#pragma unroll
        for (int ni = 0; ni < 8; ni++)
#pragma unroll
            for (int q = 0; q < 4; q++) acc[mi][ni][q] = 0.0f;

    // ---- prologue: stages 0..NS-2 -------------------------------------------
#pragma unroll
    for (int s = 0; s < NS - 1; s++) {
        const uint32_t sw = sbase + (uint32_t)s * STAGE_BYTES + swr;
        const __half* ap = agp + s * TKC;
        const __half* bp = bgp + s * TKC;
#pragma unroll
        for (int j = 0; j < 8; j++) {
            CPA16(sw + (uint32_t)j * (16 * PITCHB), ap + (size_t)(16 * j) * KDIM);
            CPA16(sw + SM_A_BYTES + (uint32_t)j * (16 * PITCHB),
                  bp + (size_t)(16 * j) * KDIM);
        }
        CP_COMMIT();
    }
    agp += 2 * TKC;                     // prefetch cursor: stage kt+2
    bgp += 2 * TKC;

    // ---- phase offset: de-phase the co-resident CTA pair --------------------
    // Classic placement pairs bids b and b+148 on one SM; offset the odd
    // member by ~half a chunk so the two CTAs' compute/load phases interleave.
    // Spin overlaps the prologue cp.async latency; output-invariant.
    {
        const int linb = blockIdx.y * gridDim.x + blockIdx.x;
        if ((linb / 148) & 1) {
            const long long t0 = clock64();
            while (clock64() - t0 < PHASE_SPIN) { }
        }
    }

    // ---- main loop ----------------------------------------------------------
    int slot = 0, pslot = 2;
    for (int kt = 0; kt < KT; kt++) {
        CP_WAIT_1();                    // stage kt landed
        __syncthreads();                // all readers of slot pslot are done

        const bool do_pf = (kt + 2) < KT;
        const uint32_t sA = sbase + (uint32_t)slot * STAGE_BYTES;
        const uint32_t aB = sA + aoff;
        const uint32_t bB = sA + boff;
        const uint32_t swp = sbase + (uint32_t)pslot * STAGE_BYTES + swr;

        // Fragments: B double-buffered across ks; A rotates per group.
        uint32_t bf[2][4][4];
        uint32_t af[2][4];

        // Preload: bf[0][0..3] + af[group 0]  (5 ldsm)
#pragma unroll
        for (int pi = 0; pi < 4; pi++)
            LDSM_X4(bf[0][pi][0], bf[0][pi][1], bf[0][pi][2], bf[0][pi][3],
                    bB + (uint32_t)pi * (16 * PITCHB));
        LDSM_X4(af[0][0], af[0][1], af[0][2], af[0][3], aB);

#pragma unroll
        for (int ks = 0; ks < 4; ks++) {            // 4 x k16 = K chunk 64
            const int cur = ks & 1, nxt = cur ^ 1;
            // Spread prefetch: quarter ks of stage kt+2 (4 cp.async)
            if (do_pf) {
#pragma unroll
                for (int j = 2 * ks; j < 2 * ks + 2; j++) {
                    CPA16(swp + (uint32_t)j * (16 * PITCHB),
                          agp + (size_t)(16 * j) * KDIM);
                    CPA16(swp + SM_A_BYTES + (uint32_t)j * (16 * PITCHB),
                          bgp + (size_t)(16 * j) * KDIM);
                }
            }
#pragma unroll
            for (int mi = 0; mi < 4; mi++) {
                const int gidx = ks * 4 + mi;
                const int ap = gidx & 1, an = ap ^ 1;   // af parity
                const int ng = gidx + 1;
                mma16(acc[mi][0], af[ap], bf[cur][0][0], bf[cur][0][2]);
                mma16(acc[mi][1], af[ap], bf[cur][0][1], bf[cur][0][3]);
                if (ng < 16)
                    LDSM_X4(af[an][0], af[an][1], af[an][2], af[an][3],
                            aB + (uint32_t)(ng & 3) * (16 * PITCHB)
                               + (uint32_t)(ng >> 2) * 32);
                mma16(acc[mi][2], af[ap], bf[cur][1][0], bf[cur][1][2]);
                mma16(acc[mi][3], af[ap], bf[cur][1][1], bf[cur][1][3]);
                if (ks < 3)             // B fragment pi=mi for ks+1 (JIT)
                    LDSM_X4(bf[nxt][mi][0], bf[nxt][mi][1],
                            bf[nxt][mi][2], bf[nxt][mi][3],
                            bB + (uint32_t)mi * (16 * PITCHB)
                               + (uint32_t)(ks + 1) * 32);
                mma16(acc[mi][4], af[ap], bf[cur][2][0], bf[cur][2][2]);
                mma16(acc[mi][5], af[ap], bf[cur][2][1], bf[cur][2][3]);
                mma16(acc[mi][6], af[ap], bf[cur][3][0], bf[cur][3][2]);
                mma16(acc[mi][7], af[ap], bf[cur][3][1], bf[cur][3][3]);
            }
        }
        CP_COMMIT();                    // one group per iteration (maybe empty)
        agp += TKC;
        bgp += TKC;
        slot = (slot == NS - 1) ? 0 : slot + 1;
        pslot = (pslot == NS - 1) ? 0 : pslot + 1;
    }

    // ---- epilogue -----------------------------------------------------------
#pragma unroll
    for (int mi = 0; mi < 4; mi++) {
        const int r0 = m0 + wm + mi * 16 + g;
        const int r1 = r0 + 8;
#pragma unroll
        for (int ni = 0; ni < 8; ni++) {
            const int cc = n0 + wn + ni * 8 + 2 * c;
            if (STORE_HALF_RELU) {
                __half* C = (__half*)Cg_;
                __half2 v0 = __floats2half2_rn(fmaxf(acc[mi][ni][0], 0.0f),
                                               fmaxf(acc[mi][ni][1], 0.0f));
                __half2 v1 = __floats2half2_rn(fmaxf(acc[mi][ni][2], 0.0f),
                                               fmaxf(acc[mi][ni][3], 0.0f));
                *(__half2*)(C + (size_t)r0 * NGLOB + cc) = v0;
                *(__half2*)(C + (size_t)r1 * NGLOB + cc) = v1;
            } else {
                float* C = (float*)Cg_;
                *(float2*)(C + (size_t)r0 * NGLOB + cc) =
                    make_float2(acc[mi][ni][0], acc[mi][ni][1]);
                *(float2*)(C + (size_t)r1 * NGLOB + cc) =
                    make_float2(acc[mi][ni][2], acc[mi][ni][3]);
            }
        }
    }
}

// ---------------------------------------------------------------------------
// Weight merge: Wm = f16_rn(W + 0.25 * B[a] @ A[a]),  W:[OUT,IN] row-major
// ---------------------------------------------------------------------------
__global__ void merge_w(const float* __restrict__ W, const float* __restrict__ A,
                        const float* __restrict__ Bm, const int* __restrict__ aid,
                        __half* __restrict__ Wm, int OUT, int IN)
{
    const int in4 = IN >> 2;
    const int i = blockIdx.x * blockDim.x + threadIdx.x;
    if (i >= OUT * in4) return;
    const int f = i / in4;
    const int d = (i - f * in4) << 2;
    const int a = aid[0];

    const float* Aa = A + (size_t)a * RANKL * IN;
    const float* Ba = Bm + (size_t)a * OUT * RANKL + (size_t)f * RANKL;
    const float b0 = Ba[0] * 0.25f, b1 = Ba[1] * 0.25f,
                b2 = Ba[2] * 0.25f, b3 = Ba[3] * 0.25f;

    float4 w = ((const float4*)W)[i];
    const float4 a0 = *(const float4*)(Aa + 0 * (size_t)IN + d);
    const float4 a1 = *(const float4*)(Aa + 1 * (size_t)IN + d);
    const float4 a2 = *(const float4*)(Aa + 2 * (size_t)IN + d);
    const float4 a3 = *(const float4*)(Aa + 3 * (size_t)IN + d);

    __half2 lo = __floats2half2_rn(w.x + b0 * a0.x + b1 * a1.x + b2 * a2.x + b3 * a3.x,
                                   w.y + b0 * a0.y + b1 * a1.y + b2 * a2.y + b3 * a3.y);
    __half2 hi = __floats2half2_rn(w.z + b0 * a0.z + b1 * a1.z + b2 * a2.z + b3 * a3.z,
                                   w.w + b0 * a0.w + b1 * a1.w + b2 * a2.w + b3 * a3.w);
    __half2* dst = (__half2*)(Wm + (size_t)i * 4);
    dst[0] = lo;
    dst[1] = hi;
}

// ---------------------------------------------------------------------------
// Activation pre-round: xh = f16_rn(x)
// ---------------------------------------------------------------------------
__global__ void to_half(const float4* __restrict__ in, __half* __restrict__ out,
                        int n4)
{
    const int i = blockIdx.x * blockDim.x + threadIdx.x;
    if (i >= n4) return;
    float4 v = in[i];
    __half2* dst = (__half2*)(out + (size_t)i * 4);
    dst[0] = __floats2half2_rn(v.x, v.y);
    dst[1] = __floats2half2_rn(v.z, v.w);
}

// ---------------------------------------------------------------------------
// Launch
// ---------------------------------------------------------------------------
extern "C" void kernel_launch(void* const* d_in, const int* in_sizes, int n_in,
                              void* d_out, int out_size)
{
    const float* x   = (const float*)d_in[0];
    const float* W1  = (const float*)d_in[1];
    const float* A1  = (const float*)d_in[2];
    const float* B1  = (const float*)d_in[3];
    const float* W2  = (const float*)d_in[4];
    const float* A2  = (const float*)d_in[5];
    const float* B2  = (const float*)d_in[6];
    const int*   aid = (const int*)d_in[7];
    float* out = (float*)d_out;

    __half *xh, *h, *w1h, *w2h;
    cudaGetSymbolAddress((void**)&xh,  g_xh);
    cudaGetSymbolAddress((void**)&h,   g_h);
    cudaGetSymbolAddress((void**)&w1h, g_w1h);
    cudaGetSymbolAddress((void**)&w2h, g_w2h);

    cudaFuncSetAttribute((gemm_f16<true, DMODEL, DFF>),
                         cudaFuncAttributeMaxDynamicSharedMemorySize, SMEM_TOTAL);
    cudaFuncSetAttribute((gemm_f16<false, DFF, DMODEL>),
                         cudaFuncAttributeMaxDynamicSharedMemorySize, SMEM_TOTAL);

    // 1) x -> fp16
    const int n4x = TOK * DMODEL / 4;
    to_half<<<(n4x + 255) / 256, 256>>>((const float4*)x, xh, n4x);

    // 2) fold LoRA into weights, round to fp16
    const int n4w = DFF * DMODEL / 4;
    merge_w<<<(n4w + 255) / 256, 256>>>(W1, A1, B1, aid, w1h, DFF, DMODEL);
    merge_w<<<(n4w + 255) / 256, 256>>>(W2, A2, B2, aid, w2h, DMODEL, DFF);

    // 3) h = f16(relu(xh @ w1h^T))     M=16384, N=4096, K=1024
    dim3 g1(DFF / TN, TOK / TM);
    gemm_f16<true, DMODEL, DFF><<<g1, 128, SMEM_TOTAL>>>(xh, w1h, (void*)h);

    // 4) out = h @ w2h^T  (fp32)       M=16384, N=1024, K=4096
    dim3 g2(DMODEL / TN, TOK / TM);
    gemm_f16<false, DFF, DMODEL><<<g2, 128, SMEM_TOTAL>>>(h, w2h, (void*)out);
}

// round 17
// speedup vs baseline: 1.5437x; 1.0285x over previous
#include <cuda_runtime.h>
#include <cuda_fp16.h>
#include <cstdint>

// ============================================================================
// FeedForwardLoRA on GB300 (sm_103) — fp16 mma.sync path, R17.
// R16 (inter-CTA phase offset) was neutral -> phase theory falsified, spin
// dropped. Remaining exposure is the per-chunk dry-pipe window at
// wait+__syncthreads+preload: at the barrier every warp has zero pending mma.
// R17: peel groups 14,15 (16 mma, operands register-resident via dedicated
// af14/af15 frags loaded pre-barrier) ACROSS the barrier, interleaved with the
// next chunk's 5 preload ldsm -> tensor pipe stays fed through the boundary.
//
//   W1h = f16_rn(W1 + 0.25 * B1[a] @ A1[a])
//   W2h = f16_rn(W2 + 0.25 * B2[a] @ A2[a])
//   xh  = f16_rn(x)
//   h   = f16_rn(relu(xh @ W1h^T))       GEMM1: M=16384 N=4096 K=1024
//   out = h @ W2h^T  (fp32 out)          GEMM2: M=16384 N=1024 K=4096
// ============================================================================

#define TOK     16384
#define DMODEL  1024
#define DFF     4096
#define RANKL   4

#define TM   128          // CTA M tile
#define TN   128          // CTA N tile
#define TKC  64           // K chunk (halves) = 128B per row
#define NS   3            // cp.async pipeline stages
#define PITCHB 144        // smem row pitch in bytes (128B data + 16B skew)

#define SM_A_BYTES (TM * PITCHB)                // 18432 B
#define SM_B_BYTES (TN * PITCHB)                // 18432 B
#define STAGE_BYTES (SM_A_BYTES + SM_B_BYTES)   // 36864 B
#define SMEM_TOTAL (NS * STAGE_BYTES)           // 110592 B (x2 CTAs = 221184/SM)

// ---------------------------------------------------------------------------
// Scratch (static __device__ arrays — the sanctioned no-alloc workaround)
// ---------------------------------------------------------------------------
__device__ __half g_xh [(size_t)TOK * DMODEL];  //  32 MB
__device__ __half g_h  [(size_t)TOK * DFF];     // 128 MB
__device__ __half g_w1h[(size_t)DFF * DMODEL];  //   8 MB
__device__ __half g_w2h[(size_t)DMODEL * DFF];  //   8 MB

// ---------------------------------------------------------------------------
// Helpers
// ---------------------------------------------------------------------------
__device__ __forceinline__ uint32_t smem_u32(const void* p) {
    uint32_t a;
    asm("{ .reg .u64 t; cvta.to.shared.u64 t, %1; cvt.u32.u64 %0, t; }"
        : "=r"(a) : "l"(p));
    return a;
}

#define CPA16(smem_addr, gptr) \
    asm volatile("cp.async.cg.shared.global [%0], [%1], 16;" \
                 :: "r"(smem_addr), "l"(gptr))
#define CP_COMMIT()  asm volatile("cp.async.commit_group;" ::: "memory")
#define CP_WAIT_1()  asm volatile("cp.async.wait_group 1;" ::: "memory")

#define LDSM_X4(r0, r1, r2, r3, addr) \
    asm volatile("ldmatrix.sync.aligned.m8n8.x4.shared.b16 {%0,%1,%2,%3}, [%4];" \
                 : "=r"(r0), "=r"(r1), "=r"(r2), "=r"(r3) : "r"(addr))

// D += A * B   (m16n8k16, fp16 inputs, fp32 accumulate)
__device__ __forceinline__ void mma16(float* d, const uint32_t* a,
                                      uint32_t b0, uint32_t b1) {
    asm volatile(
        "mma.sync.aligned.m16n8k16.row.col.f32.f16.f16.f32 "
        "{%0,%1,%2,%3}, {%4,%5,%6,%7}, {%8,%9}, {%0,%1,%2,%3};"
        : "+f"(d[0]), "+f"(d[1]), "+f"(d[2]), "+f"(d[3])
        : "r"(a[0]), "r"(a[1]), "r"(a[2]), "r"(a[3]), "r"(b0), "r"(b1));
}

// ---------------------------------------------------------------------------
// GEMM: C[M, NGLOB] = op(A[M,KDIM] @ B[NGLOB,KDIM]^T), fp16 in, fp32 acc.
// STORE_HALF_RELU: C = f16_rn(relu(.)) as half.  Else: C = fp32.
// Grid (NGLOB/TN, M/TM), 128 threads = 4 warps of 64x64 tiles (2x2 layout).
// 2 CTAs per SM. All dims divide exactly — no tails anywhere.
// ---------------------------------------------------------------------------
template <bool STORE_HALF_RELU, int KDIM, int NGLOB>
__global__ void __launch_bounds__(128, 2)
gemm_f16(const __half* __restrict__ Ag, const __half* __restrict__ Bg,
         void* __restrict__ Cg_)
{
    constexpr int KT = KDIM / TKC;
    extern __shared__ char smem[];
    const uint32_t sbase = smem_u32(smem);
    const int tid = threadIdx.x;
    const int m0 = blockIdx.y * TM;
    const int n0 = blockIdx.x * TN;

    // ---- async-load geometry: thread -> (row, 16B chunk) --------------------
    const int lrow = tid >> 3;          // 0..15
    const int lchk = tid & 7;           // 0..7

    // Advancing gmem base pointers.
    const __half* agp = Ag + (size_t)(m0 + lrow) * KDIM + lchk * 8;
    const __half* bgp = Bg + (size_t)(n0 + lrow) * KDIM + lchk * 8;
    const uint32_t swr = (uint32_t)lrow * PITCHB + (uint32_t)lchk * 16;

    // ---- compute geometry ---------------------------------------------------
    const int lane = tid & 31;
    const int w = tid >> 5;             // 0..3
    const int wm = (w & 1) * 64;        // warp M offset within CTA tile
    const int wn = (w >> 1) * 64;       // warp N offset
    const int g = lane >> 2;
    const int c = lane & 3;

    // ldmatrix lane -> (matrix id, row-in-matrix)
    const int lsub = lane >> 3;
    const int lr8  = lane & 7;
    const uint32_t arow = (uint32_t)(wm + (lsub & 1) * 8 + lr8);
    const uint32_t brow = (uint32_t)(wn + (lsub & 1) * 8 + lr8);
    const uint32_t koff = (uint32_t)(lsub >> 1) * 16;
    const uint32_t aoff = arow * PITCHB + koff;               // within stage
    const uint32_t boff = SM_A_BYTES + brow * PITCHB + koff;

    float acc[4][8][4];
#pragma unroll
    for (int mi = 0; mi < 4; mi++)
#pragma unroll
        for (int ni = 0; ni < 8; ni++)
#pragma unroll
            for (int q = 0; q < 4; q++) acc[mi][ni][q] = 0.0f;

    // ---- prologue: stages 0..NS-2 -------------------------------------------
#pragma unroll
    for (int s = 0; s < NS - 1; s++) {
        const uint32_t sw = sbase + (uint32_t)s * STAGE_BYTES + swr;
        const __half* ap = agp + s * TKC;
        const __half* bp = bgp + s * TKC;
#pragma unroll
        for (int j = 0; j < 8; j++) {
            CPA16(sw + (uint32_t)j * (16 * PITCHB), ap + (size_t)(16 * j) * KDIM);
            CPA16(sw + SM_A_BYTES + (uint32_t)j * (16 * PITCHB),
                  bp + (size_t)(16 * j) * KDIM);
        }
        CP_COMMIT();
    }
    agp += 2 * TKC;                     // prefetch cursor: stage kt+2
    bgp += 2 * TKC;

    // Fragments live across chunk iterations (peeled-tail pipeline).
    uint32_t bf[2][4][4];
    uint32_t af[2][4];
    uint32_t af14[4], af15[4];          // dedicated frags for peeled groups

    // ---- main loop ----------------------------------------------------------
    int slot = 0, pslot = 2;
    for (int kt = 0; kt < KT; kt++) {
        CP_WAIT_1();                    // stage kt landed
        __syncthreads();                // all readers of slot pslot are done

        const bool do_pf = (kt + 2) < KT;
        const uint32_t sA = sbase + (uint32_t)slot * STAGE_BYTES;
        const uint32_t aB = sA + aoff;
        const uint32_t bB = sA + boff;
        const uint32_t swp = sbase + (uint32_t)pslot * STAGE_BYTES + swr;

        if (kt > 0) {
            // Peeled groups 14,15 of the PREVIOUS chunk (operands in regs:
            // af14/af15 + bf[1]) interleaved with THIS chunk's 5 preload ldsm
            // (writing bf[0] + af[0] — disjoint from bf[1]/af14/af15).
            mma16(acc[2][0], af14, bf[1][0][0], bf[1][0][2]);
            mma16(acc[2][1], af14, bf[1][0][1], bf[1][0][3]);
            LDSM_X4(bf[0][0][0], bf[0][0][1], bf[0][0][2], bf[0][0][3],
                    bB + 0u * (16 * PITCHB));
            mma16(acc[2][2], af14, bf[1][1][0], bf[1][1][2]);
            mma16(acc[2][3], af14, bf[1][1][1], bf[1][1][3]);
            LDSM_X4(bf[0][1][0], bf[0][1][1], bf[0][1][2], bf[0][1][3],
                    bB + 1u * (16 * PITCHB));
            mma16(acc[2][4], af14, bf[1][2][0], bf[1][2][2]);
            mma16(acc[2][5], af14, bf[1][2][1], bf[1][2][3]);
            LDSM_X4(bf[0][2][0], bf[0][2][1], bf[0][2][2], bf[0][2][3],
                    bB + 2u * (16 * PITCHB));
            mma16(acc[2][6], af14, bf[1][3][0], bf[1][3][2]);
            mma16(acc[2][7], af14, bf[1][3][1], bf[1][3][3]);
            LDSM_X4(bf[0][3][0], bf[0][3][1], bf[0][3][2], bf[0][3][3],
                    bB + 3u * (16 * PITCHB));
            mma16(acc[3][0], af15, bf[1][0][0], bf[1][0][2]);
            mma16(acc[3][1], af15, bf[1][0][1], bf[1][0][3]);
            LDSM_X4(af[0][0], af[0][1], af[0][2], af[0][3], aB);
            mma16(acc[3][2], af15, bf[1][1][0], bf[1][1][2]);
            mma16(acc[3][3], af15, bf[1][1][1], bf[1][1][3]);
            mma16(acc[3][4], af15, bf[1][2][0], bf[1][2][2]);
            mma16(acc[3][5], af15, bf[1][2][1], bf[1][2][3]);
            mma16(acc[3][6], af15, bf[1][3][0], bf[1][3][2]);
            mma16(acc[3][7], af15, bf[1][3][1], bf[1][3][3]);
        } else {
            // First chunk: plain preload (5 ldsm).
#pragma unroll
            for (int pi = 0; pi < 4; pi++)
                LDSM_X4(bf[0][pi][0], bf[0][pi][1], bf[0][pi][2], bf[0][pi][3],
                        bB + (uint32_t)pi * (16 * PITCHB));
            LDSM_X4(af[0][0], af[0][1], af[0][2], af[0][3], aB);
        }

        // Groups 0..13 of this chunk (14,15 peeled into the next iteration).
#pragma unroll
        for (int ks = 0; ks < 4; ks++) {            // 4 x k16 = K chunk 64
            const int cur = ks & 1, nxt = cur ^ 1;
            // Spread prefetch: quarter ks of stage kt+2 (4 cp.async)
            if (do_pf) {
#pragma unroll
                for (int j = 2 * ks; j < 2 * ks + 2; j++) {
                    CPA16(swp + (uint32_t)j * (16 * PITCHB),
                          agp + (size_t)(16 * j) * KDIM);
                    CPA16(swp + SM_A_BYTES + (uint32_t)j * (16 * PITCHB),
                          bgp + (size_t)(16 * j) * KDIM);
                }
            }
#pragma unroll
            for (int mi = 0; mi < 4; mi++) {
                const int gidx = ks * 4 + mi;
                if (gidx >= 14) continue;           // peeled
                const int ap = gidx & 1, an = ap ^ 1;
                const int ng = gidx + 1;
                mma16(acc[mi][0], af[ap], bf[cur][0][0], bf[cur][0][2]);
                mma16(acc[mi][1], af[ap], bf[cur][0][1], bf[cur][0][3]);
                if (gidx <= 12)                     // JIT A-frag for g+1
                    LDSM_X4(af[an][0], af[an][1], af[an][2], af[an][3],
                            aB + (uint32_t)(ng & 3) * (16 * PITCHB)
                               + (uint32_t)(ng >> 2) * 32);
                mma16(acc[mi][2], af[ap], bf[cur][1][0], bf[cur][1][2]);
                mma16(acc[mi][3], af[ap], bf[cur][1][1], bf[cur][1][3]);
                if (ks < 3)             // B fragment pi=mi for ks+1 (JIT)
                    LDSM_X4(bf[nxt][mi][0], bf[nxt][mi][1],
                            bf[nxt][mi][2], bf[nxt][mi][3],
                            bB + (uint32_t)mi * (16 * PITCHB)
                               + (uint32_t)(ks + 1) * 32);
                if (gidx == 13)                     // pre-barrier peel frags
                    LDSM_X4(af14[0], af14[1], af14[2], af14[3],
                            aB + 2u * (16 * PITCHB) + 3u * 32);
                mma16(acc[mi][4], af[ap], bf[cur][2][0], bf[cur][2][2]);
                mma16(acc[mi][5], af[ap], bf[cur][2][1], bf[cur][2][3]);
                if (gidx == 13)
                    LDSM_X4(af15[0], af15[1], af15[2], af15[3],
                            aB + 3u * (16 * PITCHB) + 3u * 32);
                mma16(acc[mi][6], af[ap], bf[cur][3][0], bf[cur][3][2]);
                mma16(acc[mi][7], af[ap], bf[cur][3][1], bf[cur][3][3]);
            }
        }
        CP_COMMIT();                    // one group per iteration (maybe empty)
        agp += TKC;
        bgp += TKC;
        slot = (slot == NS - 1) ? 0 : slot + 1;
        pslot = (pslot == NS - 1) ? 0 : pslot + 1;
    }

    // Final peeled tail: groups 14,15 of chunk KT-1 (operands in regs).
    mma16(acc[2][0], af14, bf[1][0][0], bf[1][0][2]);
    mma16(acc[2][1], af14, bf[1][0][1], bf[1][0][3]);
    mma16(acc[2][2], af14, bf[1][1][0], bf[1][1][2]);
    mma16(acc[2][3], af14, bf[1][1][1], bf[1][1][3]);
    mma16(acc[2][4], af14, bf[1][2][0], bf[1][2][2]);
    mma16(acc[2][5], af14, bf[1][2][1], bf[1][2][3]);
    mma16(acc[2][6], af14, bf[1][3][0], bf[1][3][2]);
    mma16(acc[2][7], af14, bf[1][3][1], bf[1][3][3]);
    mma16(acc[3][0], af15, bf[1][0][0], bf[1][0][2]);
    mma16(acc[3][1], af15, bf[1][0][1], bf[1][0][3]);
    mma16(acc[3][2], af15, bf[1][1][0], bf[1][1][2]);
    mma16(acc[3][3], af15, bf[1][1][1], bf[1][1][3]);
    mma16(acc[3][4], af15, bf[1][2][0], bf[1][2][2]);
    mma16(acc[3][5], af15, bf[1][2][1], bf[1][2][3]);
    mma16(acc[3][6], af15, bf[1][3][0], bf[1][3][2]);
    mma16(acc[3][7], af15, bf[1][3][1], bf[1][3][3]);

    // ---- epilogue -----------------------------------------------------------
#pragma unroll
    for (int mi = 0; mi < 4; mi++) {
        const int r0 = m0 + wm + mi * 16 + g;
        const int r1 = r0 + 8;
#pragma unroll
        for (int ni = 0; ni < 8; ni++) {
            const int cc = n0 + wn + ni * 8 + 2 * c;
            if (STORE_HALF_RELU) {
                __half* C = (__half*)Cg_;
                __half2 v0 = __floats2half2_rn(fmaxf(acc[mi][ni][0], 0.0f),
                                               fmaxf(acc[mi][ni][1], 0.0f));
                __half2 v1 = __floats2half2_rn(fmaxf(acc[mi][ni][2], 0.0f),
                                               fmaxf(acc[mi][ni][3], 0.0f));
                *(__half2*)(C + (size_t)r0 * NGLOB + cc) = v0;
                *(__half2*)(C + (size_t)r1 * NGLOB + cc) = v1;
            } else {
                float* C = (float*)Cg_;
                *(float2*)(C + (size_t)r0 * NGLOB + cc) =
                    make_float2(acc[mi][ni][0], acc[mi][ni][1]);
                *(float2*)(C + (size_t)r1 * NGLOB + cc) =
                    make_float2(acc[mi][ni][2], acc[mi][ni][3]);
            }
        }
    }
}

// ---------------------------------------------------------------------------
// Weight merge: Wm = f16_rn(W + 0.25 * B[a] @ A[a]),  W:[OUT,IN] row-major
// ---------------------------------------------------------------------------
__global__ void merge_w(const float* __restrict__ W, const float* __restrict__ A,
                        const float* __restrict__ Bm, const int* __restrict__ aid,
                        __half* __restrict__ Wm, int OUT, int IN)
{
    const int in4 = IN >> 2;
    const int i = blockIdx.x * blockDim.x + threadIdx.x;
    if (i >= OUT * in4) return;
    const int f = i / in4;
    const int d = (i - f * in4) << 2;
    const int a = aid[0];

    const float* Aa = A + (size_t)a * RANKL * IN;
    const float* Ba = Bm + (size_t)a * OUT * RANKL + (size_t)f * RANKL;
    const float b0 = Ba[0] * 0.25f, b1 = Ba[1] * 0.25f,
                b2 = Ba[2] * 0.25f, b3 = Ba[3] * 0.25f;

    float4 w = ((const float4*)W)[i];
    const float4 a0 = *(const float4*)(Aa + 0 * (size_t)IN + d);
    const float4 a1 = *(const float4*)(Aa + 1 * (size_t)IN + d);
    const float4 a2 = *(const float4*)(Aa + 2 * (size_t)IN + d);
    const float4 a3 = *(const float4*)(Aa + 3 * (size_t)IN + d);

    __half2 lo = __floats2half2_rn(w.x + b0 * a0.x + b1 * a1.x + b2 * a2.x + b3 * a3.x,
                                   w.y + b0 * a0.y + b1 * a1.y + b2 * a2.y + b3 * a3.y);
    __half2 hi = __floats2half2_rn(w.z + b0 * a0.z + b1 * a1.z + b2 * a2.z + b3 * a3.z,
                                   w.w + b0 * a0.w + b1 * a1.w + b2 * a2.w + b3 * a3.w);
    __half2* dst = (__half2*)(Wm + (size_t)i * 4);
    dst[0] = lo;
    dst[1] = hi;
}

// ---------------------------------------------------------------------------
// Activation pre-round: xh = f16_rn(x)
// ---------------------------------------------------------------------------
__global__ void to_half(const float4* __restrict__ in, __half* __restrict__ out,
                        int n4)
{
    const int i = blockIdx.x * blockDim.x + threadIdx.x;
    if (i >= n4) return;
    float4 v = in[i];
    __half2* dst = (__half2*)(out + (size_t)i * 4);
    dst[0] = __floats2half2_rn(v.x, v.y);
    dst[1] = __floats2half2_rn(v.z, v.w);
}

// ---------------------------------------------------------------------------
// Launch
// ---------------------------------------------------------------------------
extern "C" void kernel_launch(void* const* d_in, const int* in_sizes, int n_in,
                              void* d_out, int out_size)
{
    const float* x   = (const float*)d_in[0];
    const float* W1  = (const float*)d_in[1];
    const float* A1  = (const float*)d_in[2];
    const float* B1  = (const float*)d_in[3];
    const float* W2  = (const float*)d_in[4];
    const float* A2  = (const float*)d_in[5];
    const float* B2  = (const float*)d_in[6];
    const int*   aid = (const int*)d_in[7];
    float* out = (float*)d_out;

    __half *xh, *h, *w1h, *w2h;
    cudaGetSymbolAddress((void**)&xh,  g_xh);
    cudaGetSymbolAddress((void**)&h,   g_h);
    cudaGetSymbolAddress((void**)&w1h, g_w1h);
    cudaGetSymbolAddress((void**)&w2h, g_w2h);

    cudaFuncSetAttribute((gemm_f16<true, DMODEL, DFF>),
                         cudaFuncAttributeMaxDynamicSharedMemorySize, SMEM_TOTAL);
    cudaFuncSetAttribute((gemm_f16<false, DFF, DMODEL>),
                         cudaFuncAttributeMaxDynamicSharedMemorySize, SMEM_TOTAL);

    // 1) x -> fp16
    const int n4x = TOK * DMODEL / 4;
    to_half<<<(n4x + 255) / 256, 256>>>((const float4*)x, xh, n4x);

    // 2) fold LoRA into weights, round to fp16
    const int n4w = DFF * DMODEL / 4;
    merge_w<<<(n4w + 255) / 256, 256>>>(W1, A1, B1, aid, w1h, DFF, DMODEL);
    merge_w<<<(n4w + 255) / 256, 256>>>(W2, A2, B2, aid, w2h, DMODEL, DFF);

    // 3) h = f16(relu(xh @ w1h^T))     M=16384, N=4096, K=1024
    dim3 g1(DFF / TN, TOK / TM);
    gemm_f16<true, DMODEL, DFF><<<g1, 128, SMEM_TOTAL>>>(xh, w1h, (void*)h);

    // 4) out = h @ w2h^T  (fp32)       M=16384, N=1024, K=4096
    dim3 g2(DMODEL / TN, TOK / TM);
    gemm_f16<false, DFF, DMODEL><<<g2, 128, SMEM_TOTAL>>>(h, w2h, (void*)out);
}